// round 10
// baseline (speedup 1.0000x reference)
#include <cuda_runtime.h>
#include <cstdint>

#define N_USERS 100000
#define N_ITEMS 60000
#define N_NODES 160000
#define D 64
#define D4 16              // D in float4 units
#define NNZ 1280000
#define EPS 0.1f
#define SCAN_BS 1024
#define NB_SCAN ((N_NODES + SCAN_BS - 1) / SCAN_BS)   // 157

// ---------------- scratch (static device globals; no allocation) -------------
__device__ int   g_cnt[N_NODES];                 // zero-init invariant
__device__ int   g_rowptr[N_NODES + 1];
__device__ int   g_cursor[N_NODES];
__device__ unsigned long long g_state[NB_SCAN];  // decoupled-lookback state
__device__ int2  g_edges[NNZ];                   // packed (col, val-bits)
__device__ float g_ego1[(size_t)N_NODES * D];
__device__ float g_ego2[(size_t)N_NODES * D];

// ---------------- histogram (block 0 also resets lookback state) -------------
__global__ void k_hist(const int* __restrict__ rows) {
    if (blockIdx.x == 0 && threadIdx.x < NB_SCAN) g_state[threadIdx.x] = 0ULL;
    int e = blockIdx.x * blockDim.x + threadIdx.x;
    if (e < NNZ) atomicAdd(&g_cnt[rows[e]], 1);
}

// ---------------- single-pass exclusive scan with decoupled lookback ---------
__global__ void k_scan() {
    __shared__ int wsum[32];
    __shared__ int s_running;
    const int bid  = blockIdx.x;
    const int i    = bid * SCAN_BS + threadIdx.x;
    const int lane = threadIdx.x & 31;
    const int wid  = threadIdx.x >> 5;

    int v = (i < N_NODES) ? g_cnt[i] : 0;
    if (i < N_NODES) g_cnt[i] = 0;

    int s = v;
    #pragma unroll
    for (int d = 1; d < 32; d <<= 1) {
        int t = __shfl_up_sync(0xffffffffu, s, d);
        if (lane >= d) s += t;
    }
    if (lane == 31) wsum[wid] = s;
    __syncthreads();
    if (wid == 0) {
        int ws = wsum[lane];
        #pragma unroll
        for (int d = 1; d < 32; d <<= 1) {
            int t = __shfl_up_sync(0xffffffffu, ws, d);
            if (lane >= d) ws += t;
        }
        wsum[lane] = ws;
    }
    __syncthreads();
    const int incl  = s + (wid ? wsum[wid - 1] : 0);
    const int total = wsum[31];

    if (threadIdx.x == 0) {
        unsigned long long pk = ((bid == 0) ? (2ULL << 32) : (1ULL << 32))
                                | (unsigned)total;
        __threadfence();
        atomicExch(&g_state[bid], pk);
        if (bid == 0) { s_running = 0; g_rowptr[N_NODES] = NNZ; }
    }

    if (wid == 0 && bid > 0) {
        int running = 0;
        int pb = bid - 1;
        while (true) {
            int idx = pb - lane;
            unsigned long long st = 0ULL;
            if (idx >= 0) {
                do {
                    st = *(volatile unsigned long long*)&g_state[idx];
                } while ((st >> 32) == 0ULL);
            }
            unsigned pm = __ballot_sync(0xffffffffu, (idx >= 0) && ((st >> 32) == 2ULL));
            int val = (idx >= 0) ? (int)(st & 0xffffffffULL) : 0;
            if (pm) {
                int fp = __ffs(pm) - 1;
                int contrib = (lane <= fp) ? val : 0;
                #pragma unroll
                for (int m = 16; m; m >>= 1) contrib += __shfl_xor_sync(0xffffffffu, contrib, m);
                running += contrib;
                break;
            } else {
                int contrib = val;
                #pragma unroll
                for (int m = 16; m; m >>= 1) contrib += __shfl_xor_sync(0xffffffffu, contrib, m);
                running += contrib;
                pb -= 32;
            }
        }
        if (lane == 0) {
            __threadfence();
            atomicExch(&g_state[bid], (2ULL << 32) | (unsigned)(total + running));
            s_running = running;
        }
    }
    __syncthreads();

    const int excl = incl - v + s_running;
    if (i < N_NODES) { g_rowptr[i] = excl; g_cursor[i] = excl; }
}

// ---------------- scatter COO -> CSR (packed edges) ---------------------------
__global__ void k_scatter(const int* __restrict__ rows,
                          const int* __restrict__ cols,
                          const float* __restrict__ vals) {
    int e = blockIdx.x * blockDim.x + threadIdx.x;
    if (e < NNZ) {
        int r = rows[e];
        int p = atomicAdd(&g_cursor[r], 1);
        g_edges[p] = make_int2(cols[e], __float_as_int(vals[e]));
    }
}

// ---------------- fused SpMM + noise-perturb + epilogue ----------------------
// TWO rows per warp via half-warps; lane holds a float4. First stage is an
// UNROLL-8 burst (most Poisson(8) rows finish the gather phase in one L2
// round-trip), then unroll-4, then scalar tail. SPLIT removes the user/item
// base select for layers 1/2 (single contiguous x buffer).
template <int K, bool SPLIT>
__global__ void __launch_bounds__(256, 5)
k_spmm(const float4* __restrict__ xu,
       const float4* __restrict__ xi_adj,          // xi - N_USERS*D4 (SPLIT only)
       const float4* __restrict__ noise,           // offset to layer K
       const float4* __restrict__ prevA,           // K==2: ego1
       const float4* __restrict__ prevB,           // K==2: ego2
       float4* __restrict__ yout,                  // K==0/1
       float4* __restrict__ out4)                  // d_out as float4
{
    const int gw   = (blockIdx.x * blockDim.x + threadIdx.x) >> 5;
    const int lane = threadIdx.x & 31;
    const int half = lane >> 4;
    const unsigned fl = lane & 15;
    const int row  = gw * 2 + half;
    if (row >= N_NODES) return;

    int p   = __ldg(&g_rowptr[row]);
    int end = __ldg(&g_rowptr[row + 1]);

    float4 acc = make_float4(0.f, 0.f, 0.f, 0.f);

    #define GATHER(e) (SPLIT \
        ? __ldg((((e).x < N_USERS) ? xu : xi_adj) + ((unsigned)(e).x * D4 + fl)) \
        : __ldg(xu + ((unsigned)(e).x * D4 + fl)))
    #define FMA4(v, t) do { \
        acc.x = fmaf((v), (t).x, acc.x); \
        acc.y = fmaf((v), (t).y, acc.y); \
        acc.z = fmaf((v), (t).z, acc.z); \
        acc.w = fmaf((v), (t).w, acc.w); } while (0)

    // stage 1: unroll-8 bursts (one L2 round-trip for deg<=8 rows)
    for (; p + 8 <= end; p += 8) {
        const int2 e0 = __ldg(&g_edges[p + 0]);
        const int2 e1 = __ldg(&g_edges[p + 1]);
        const int2 e2 = __ldg(&g_edges[p + 2]);
        const int2 e3 = __ldg(&g_edges[p + 3]);
        const int2 e4 = __ldg(&g_edges[p + 4]);
        const int2 e5 = __ldg(&g_edges[p + 5]);
        const int2 e6 = __ldg(&g_edges[p + 6]);
        const int2 e7 = __ldg(&g_edges[p + 7]);
        const float4 t0 = GATHER(e0);
        const float4 t1 = GATHER(e1);
        const float4 t2 = GATHER(e2);
        const float4 t3 = GATHER(e3);
        const float4 t4 = GATHER(e4);
        const float4 t5 = GATHER(e5);
        const float4 t6 = GATHER(e6);
        const float4 t7 = GATHER(e7);
        FMA4(__int_as_float(e0.y), t0);
        FMA4(__int_as_float(e1.y), t1);
        FMA4(__int_as_float(e2.y), t2);
        FMA4(__int_as_float(e3.y), t3);
        FMA4(__int_as_float(e4.y), t4);
        FMA4(__int_as_float(e5.y), t5);
        FMA4(__int_as_float(e6.y), t6);
        FMA4(__int_as_float(e7.y), t7);
    }
    // stage 2: one unroll-4 block
    if (p + 4 <= end) {
        const int2 e0 = __ldg(&g_edges[p + 0]);
        const int2 e1 = __ldg(&g_edges[p + 1]);
        const int2 e2 = __ldg(&g_edges[p + 2]);
        const int2 e3 = __ldg(&g_edges[p + 3]);
        const float4 t0 = GATHER(e0);
        const float4 t1 = GATHER(e1);
        const float4 t2 = GATHER(e2);
        const float4 t3 = GATHER(e3);
        FMA4(__int_as_float(e0.y), t0);
        FMA4(__int_as_float(e1.y), t1);
        FMA4(__int_as_float(e2.y), t2);
        FMA4(__int_as_float(e3.y), t3);
        p += 4;
    }
    // scalar tail: 0-3 edges
    for (; p < end; ++p) {
        const int2 e0 = __ldg(&g_edges[p]);
        const float4 t0 = GATHER(e0);
        FMA4(__int_as_float(e0.y), t0);
    }
    #undef GATHER
    #undef FMA4

    // noise loaded after the loop (regs not live across the edge walk)
    const size_t off = (size_t)row * D4 + fl;
    const float4 nk  = __ldcs(noise + off);

    float ss = nk.x * nk.x + nk.y * nk.y + nk.z * nk.z + nk.w * nk.w;
    #pragma unroll
    for (int m = 8; m; m >>= 1) ss += __shfl_xor_sync(0xffffffffu, ss, m);
    const float inv = EPS / fmaxf(sqrtf(ss), 1e-12f);
    float4 r = acc;
    r.x += ((acc.x > 0.f) ? 1.f : ((acc.x < 0.f) ? -1.f : 0.f)) * nk.x * inv;
    r.y += ((acc.y > 0.f) ? 1.f : ((acc.y < 0.f) ? -1.f : 0.f)) * nk.y * inv;
    r.z += ((acc.z > 0.f) ? 1.f : ((acc.z < 0.f) ? -1.f : 0.f)) * nk.z * inv;
    r.w += ((acc.w > 0.f) ? 1.f : ((acc.w < 0.f) ? -1.f : 0.f)) * nk.w * inv;

    if (K == 0) {
        yout[off] = r;                                     // ego1 (reused next layer)
        __stcs(out4 + (size_t)N_NODES * D4 + off, r);      // CL region: stream out
    } else if (K == 1) {
        yout[off] = r;                                     // ego2
    } else {
        const float4 pa = __ldcs(prevA + off);             // ego1: last use
        const float4 pb = __ldg(prevB + off);              // ego2: L2-hot
        const float third = 1.f / 3.f;
        float4 f;
        f.x = (pa.x + pb.x + r.x) * third;
        f.y = (pa.y + pb.y + r.y) * third;
        f.z = (pa.z + pb.z + r.z) * third;
        f.w = (pa.w + pb.w + r.w) * third;
        __stcs(out4 + off, f);                             // final region: stream out
    }
}

// ---------------- launch ------------------------------------------------------
extern "C" void kernel_launch(void* const* d_in, const int* in_sizes, int n_in,
                              void* d_out, int out_size) {
    const float* user_emb = (const float*)d_in[0];
    const float* item_emb = (const float*)d_in[1];
    const float* adj_vals = (const float*)d_in[2];
    const float* noise    = (const float*)d_in[3];
    const int*   adj_rows = (const int*)d_in[4];
    const int*   adj_cols = (const int*)d_in[5];
    float4* out4 = (float4*)d_out;

    // --- build CSR from COO ---
    k_hist<<<NNZ / 256, 256>>>(adj_rows);
    k_scan<<<NB_SCAN, SCAN_BS>>>();
    k_scatter<<<NNZ / 256, 256>>>(adj_rows, adj_cols, adj_vals);

    static float4* ego1 = nullptr;
    static float4* ego2 = nullptr;
    if (!ego1) {
        void* p;
        cudaGetSymbolAddress(&p, g_ego1); ego1 = (float4*)p;
        cudaGetSymbolAddress(&p, g_ego2); ego2 = (float4*)p;
    }

    const float4* noise4 = (const float4*)noise;
    const int threads = 256;                               // 8 warps = 16 rows/block
    const int blocks  = N_NODES / 16;                      // 10000

    // layer 0: split tables; xi_adj = item_emb - N_USERS*D4 (pointer only formed)
    k_spmm<0, true><<<blocks, threads>>>((const float4*)user_emb,
                                   (const float4*)item_emb - (size_t)N_USERS * D4,
                                   noise4,
                                   nullptr, nullptr, ego1, out4);
    // layer 1: x = ego1 contiguous (no select)
    k_spmm<1, false><<<blocks, threads>>>((const float4*)ego1,
                                   nullptr,
                                   noise4 + (size_t)1 * N_NODES * D4,
                                   nullptr, nullptr, ego2, out4);
    // layer 2: x = ego2; epilogue writes final = (ego1+ego2+ego3)/3
    k_spmm<2, false><<<blocks, threads>>>((const float4*)ego2,
                                   nullptr,
                                   noise4 + (size_t)2 * N_NODES * D4,
                                   (const float4*)ego1, (const float4*)ego2,
                                   nullptr, out4);
}

// round 11
// speedup vs baseline: 1.1271x; 1.1271x over previous
#include <cuda_runtime.h>
#include <cstdint>

#define N_USERS 100000
#define N_ITEMS 60000
#define N_NODES 160000
#define D 64
#define D4 16              // D in float4 units
#define NNZ 1280000
#define EPS 0.1f
#define SCAN_BS 1024
#define NB_SCAN ((N_NODES + SCAN_BS - 1) / SCAN_BS)   // 157

// ---------------- scratch (static device globals; no allocation) -------------
__device__ int   g_cnt[N_NODES];                 // zero-init invariant
__device__ int   g_rowptr[N_NODES + 1];
__device__ int   g_cursor[N_NODES];
__device__ unsigned long long g_state[NB_SCAN];  // decoupled-lookback state
__device__ int2  g_edges[NNZ];                   // packed (col, val-bits)
__device__ float g_ego1[(size_t)N_NODES * D];
__device__ float g_ego2[(size_t)N_NODES * D];

// ---------------- histogram (block 0 also resets lookback state) -------------
__global__ void k_hist(const int* __restrict__ rows) {
    if (blockIdx.x == 0 && threadIdx.x < NB_SCAN) g_state[threadIdx.x] = 0ULL;
    int e = blockIdx.x * blockDim.x + threadIdx.x;
    if (e < NNZ) atomicAdd(&g_cnt[rows[e]], 1);
}

// ---------------- single-pass exclusive scan with decoupled lookback ---------
__global__ void k_scan() {
    __shared__ int wsum[32];
    __shared__ int s_running;
    const int bid  = blockIdx.x;
    const int i    = bid * SCAN_BS + threadIdx.x;
    const int lane = threadIdx.x & 31;
    const int wid  = threadIdx.x >> 5;

    int v = (i < N_NODES) ? g_cnt[i] : 0;
    if (i < N_NODES) g_cnt[i] = 0;

    int s = v;
    #pragma unroll
    for (int d = 1; d < 32; d <<= 1) {
        int t = __shfl_up_sync(0xffffffffu, s, d);
        if (lane >= d) s += t;
    }
    if (lane == 31) wsum[wid] = s;
    __syncthreads();
    if (wid == 0) {
        int ws = wsum[lane];
        #pragma unroll
        for (int d = 1; d < 32; d <<= 1) {
            int t = __shfl_up_sync(0xffffffffu, ws, d);
            if (lane >= d) ws += t;
        }
        wsum[lane] = ws;
    }
    __syncthreads();
    const int incl  = s + (wid ? wsum[wid - 1] : 0);
    const int total = wsum[31];

    if (threadIdx.x == 0) {
        unsigned long long pk = ((bid == 0) ? (2ULL << 32) : (1ULL << 32))
                                | (unsigned)total;
        __threadfence();
        atomicExch(&g_state[bid], pk);
        if (bid == 0) { s_running = 0; g_rowptr[N_NODES] = NNZ; }
    }

    if (wid == 0 && bid > 0) {
        int running = 0;
        int pb = bid - 1;
        while (true) {
            int idx = pb - lane;
            unsigned long long st = 0ULL;
            if (idx >= 0) {
                do {
                    st = *(volatile unsigned long long*)&g_state[idx];
                } while ((st >> 32) == 0ULL);
            }
            unsigned pm = __ballot_sync(0xffffffffu, (idx >= 0) && ((st >> 32) == 2ULL));
            int val = (idx >= 0) ? (int)(st & 0xffffffffULL) : 0;
            if (pm) {
                int fp = __ffs(pm) - 1;
                int contrib = (lane <= fp) ? val : 0;
                #pragma unroll
                for (int m = 16; m; m >>= 1) contrib += __shfl_xor_sync(0xffffffffu, contrib, m);
                running += contrib;
                break;
            } else {
                int contrib = val;
                #pragma unroll
                for (int m = 16; m; m >>= 1) contrib += __shfl_xor_sync(0xffffffffu, contrib, m);
                running += contrib;
                pb -= 32;
            }
        }
        if (lane == 0) {
            __threadfence();
            atomicExch(&g_state[bid], (2ULL << 32) | (unsigned)(total + running));
            s_running = running;
        }
    }
    __syncthreads();

    const int excl = incl - v + s_running;
    if (i < N_NODES) { g_rowptr[i] = excl; g_cursor[i] = excl; }
}

// ---------------- scatter COO -> CSR (packed edges) ---------------------------
__global__ void k_scatter(const int* __restrict__ rows,
                          const int* __restrict__ cols,
                          const float* __restrict__ vals) {
    int e = blockIdx.x * blockDim.x + threadIdx.x;
    if (e < NNZ) {
        int r = rows[e];
        int p = atomicAdd(&g_cursor[r], 1);
        g_edges[p] = make_int2(cols[e], __float_as_int(vals[e]));
    }
}

// ---------------- fused SpMM + noise-perturb + epilogue ----------------------
// TWO rows per warp via half-warps; lane holds a float4. The 0-3 tail edges
// are PEELED UPFRONT into an independent accumulator chain so they overlap the
// whole quad pipeline (max instead of sum of latencies). Main loop: R9's
// software-pipelined unroll-4 over an exact multiple of 4, no leftover checks.
// SPLIT removes the user/item base select for layers 1/2.
template <int K, bool SPLIT>
__global__ void __launch_bounds__(256, 6)
k_spmm(const float4* __restrict__ xu,
       const float4* __restrict__ xi_adj,          // xi - N_USERS*D4 (SPLIT only)
       const float4* __restrict__ noise,           // offset to layer K
       const float4* __restrict__ prevA,           // K==2: ego1
       const float4* __restrict__ prevB,           // K==2: ego2
       float4* __restrict__ yout,                  // K==0/1
       float4* __restrict__ out4)                  // d_out as float4
{
    const int gw   = (blockIdx.x * blockDim.x + threadIdx.x) >> 5;
    const int lane = threadIdx.x & 31;
    const int half = lane >> 4;
    const unsigned fl = lane & 15;
    const int row  = gw * 2 + half;
    if (row >= N_NODES) return;

    int p   = __ldg(&g_rowptr[row]);
    int end = __ldg(&g_rowptr[row + 1]);

    float4 acc  = make_float4(0.f, 0.f, 0.f, 0.f);
    float4 tacc = make_float4(0.f, 0.f, 0.f, 0.f);

    #define GATHER(e) (SPLIT \
        ? __ldg((((e).x < N_USERS) ? xu : xi_adj) + ((unsigned)(e).x * D4 + fl)) \
        : __ldg(xu + ((unsigned)(e).x * D4 + fl)))
    #define FMA4(d, v, t) do { \
        d.x = fmaf((v), (t).x, d.x); \
        d.y = fmaf((v), (t).y, d.y); \
        d.z = fmaf((v), (t).z, d.z); \
        d.w = fmaf((v), (t).w, d.w); } while (0)

    // ---- tail peel: 0-3 edges at the end, independent chain, issued FIRST ----
    const int rem = (end - p) & 3;
    const int qend = end - rem;                    // main loop covers [p, qend)
    if (rem > 0) {
        const int2 a = __ldg(&g_edges[qend]);
        const float4 t = GATHER(a);
        FMA4(tacc, __int_as_float(a.y), t);
    }
    if (rem > 1) {
        const int2 a = __ldg(&g_edges[qend + 1]);
        const float4 t = GATHER(a);
        FMA4(tacc, __int_as_float(a.y), t);
    }
    if (rem > 2) {
        const int2 a = __ldg(&g_edges[qend + 2]);
        const float4 t = GATHER(a);
        FMA4(tacc, __int_as_float(a.y), t);
    }

    // ---- main: software-pipelined unroll-4, exact multiple of 4 ----
    if (p < qend) {
        int2 e0 = __ldg(&g_edges[p + 0]);
        int2 e1 = __ldg(&g_edges[p + 1]);
        int2 e2 = __ldg(&g_edges[p + 2]);
        int2 e3 = __ldg(&g_edges[p + 3]);
        for (; p + 8 <= qend; p += 4) {
            const float4 t0 = GATHER(e0);
            const float4 t1 = GATHER(e1);
            const float4 t2 = GATHER(e2);
            const float4 t3 = GATHER(e3);
            const int2 n0 = __ldg(&g_edges[p + 4]);
            const int2 n1 = __ldg(&g_edges[p + 5]);
            const int2 n2 = __ldg(&g_edges[p + 6]);
            const int2 n3 = __ldg(&g_edges[p + 7]);
            FMA4(acc, __int_as_float(e0.y), t0);
            FMA4(acc, __int_as_float(e1.y), t1);
            FMA4(acc, __int_as_float(e2.y), t2);
            FMA4(acc, __int_as_float(e3.y), t3);
            e0 = n0; e1 = n1; e2 = n2; e3 = n3;
        }
        const float4 t0 = GATHER(e0);
        const float4 t1 = GATHER(e1);
        const float4 t2 = GATHER(e2);
        const float4 t3 = GATHER(e3);
        FMA4(acc, __int_as_float(e0.y), t0);
        FMA4(acc, __int_as_float(e1.y), t1);
        FMA4(acc, __int_as_float(e2.y), t2);
        FMA4(acc, __int_as_float(e3.y), t3);
    }
    acc.x += tacc.x; acc.y += tacc.y; acc.z += tacc.z; acc.w += tacc.w;
    #undef GATHER
    #undef FMA4

    // noise loaded after the loop (regs not live across the edge walk)
    const size_t off = (size_t)row * D4 + fl;
    const float4 nk  = __ldcs(noise + off);

    float ss = nk.x * nk.x + nk.y * nk.y + nk.z * nk.z + nk.w * nk.w;
    #pragma unroll
    for (int m = 8; m; m >>= 1) ss += __shfl_xor_sync(0xffffffffu, ss, m);
    const float inv = EPS / fmaxf(sqrtf(ss), 1e-12f);
    float4 r = acc;
    r.x += ((acc.x > 0.f) ? 1.f : ((acc.x < 0.f) ? -1.f : 0.f)) * nk.x * inv;
    r.y += ((acc.y > 0.f) ? 1.f : ((acc.y < 0.f) ? -1.f : 0.f)) * nk.y * inv;
    r.z += ((acc.z > 0.f) ? 1.f : ((acc.z < 0.f) ? -1.f : 0.f)) * nk.z * inv;
    r.w += ((acc.w > 0.f) ? 1.f : ((acc.w < 0.f) ? -1.f : 0.f)) * nk.w * inv;

    if (K == 0) {
        yout[off] = r;                                     // ego1 (reused next layer)
        __stcs(out4 + (size_t)N_NODES * D4 + off, r);      // CL region: stream out
    } else if (K == 1) {
        yout[off] = r;                                     // ego2
    } else {
        const float4 pa = __ldcs(prevA + off);             // ego1: last use
        const float4 pb = __ldg(prevB + off);              // ego2: L2-hot
        const float third = 1.f / 3.f;
        float4 f;
        f.x = (pa.x + pb.x + r.x) * third;
        f.y = (pa.y + pb.y + r.y) * third;
        f.z = (pa.z + pb.z + r.z) * third;
        f.w = (pa.w + pb.w + r.w) * third;
        __stcs(out4 + off, f);                             // final region: stream out
    }
}

// ---------------- launch ------------------------------------------------------
extern "C" void kernel_launch(void* const* d_in, const int* in_sizes, int n_in,
                              void* d_out, int out_size) {
    const float* user_emb = (const float*)d_in[0];
    const float* item_emb = (const float*)d_in[1];
    const float* adj_vals = (const float*)d_in[2];
    const float* noise    = (const float*)d_in[3];
    const int*   adj_rows = (const int*)d_in[4];
    const int*   adj_cols = (const int*)d_in[5];
    float4* out4 = (float4*)d_out;

    // --- build CSR from COO ---
    k_hist<<<NNZ / 256, 256>>>(adj_rows);
    k_scan<<<NB_SCAN, SCAN_BS>>>();
    k_scatter<<<NNZ / 256, 256>>>(adj_rows, adj_cols, adj_vals);

    static float4* ego1 = nullptr;
    static float4* ego2 = nullptr;
    if (!ego1) {
        void* p;
        cudaGetSymbolAddress(&p, g_ego1); ego1 = (float4*)p;
        cudaGetSymbolAddress(&p, g_ego2); ego2 = (float4*)p;
    }

    const float4* noise4 = (const float4*)noise;
    const int threads = 256;                               // 8 warps = 16 rows/block
    const int blocks  = N_NODES / 16;                      // 10000

    // layer 0: split tables; xi_adj = item_emb - N_USERS*D4 (pointer only formed)
    k_spmm<0, true><<<blocks, threads>>>((const float4*)user_emb,
                                   (const float4*)item_emb - (size_t)N_USERS * D4,
                                   noise4,
                                   nullptr, nullptr, ego1, out4);
    // layer 1: x = ego1 contiguous (no select)
    k_spmm<1, false><<<blocks, threads>>>((const float4*)ego1,
                                   nullptr,
                                   noise4 + (size_t)1 * N_NODES * D4,
                                   nullptr, nullptr, ego2, out4);
    // layer 2: x = ego2; epilogue writes final = (ego1+ego2+ego3)/3
    k_spmm<2, false><<<blocks, threads>>>((const float4*)ego2,
                                   nullptr,
                                   noise4 + (size_t)2 * N_NODES * D4,
                                   (const float4*)ego1, (const float4*)ego2,
                                   nullptr, out4);
}

// round 12
// speedup vs baseline: 1.2139x; 1.0770x over previous
#include <cuda_runtime.h>
#include <cstdint>

#define N_USERS 100000
#define N_ITEMS 60000
#define N_NODES 160000
#define D 64
#define D4 16              // D in float4 units
#define NNZ 1280000
#define EPS 0.1f
#define SCAN_BS 1024
#define NB_SCAN ((N_NODES + SCAN_BS - 1) / SCAN_BS)   // 157

// ---------------- scratch (static device globals; no allocation) -------------
__device__ int   g_cnt[N_NODES];                 // zero-init invariant
__device__ int   g_rowptr[N_NODES + 1];
__device__ int   g_cursor[N_NODES];
__device__ unsigned long long g_state[NB_SCAN];  // decoupled-lookback state
__device__ int2  g_edges[NNZ];                   // packed (col, val-bits)
__device__ float g_ego1[(size_t)N_NODES * D];
__device__ float g_ego2[(size_t)N_NODES * D];

// ---------------- histogram: 4 edges/thread via int4 loads -------------------
__global__ void k_hist(const int4* __restrict__ rows4) {
    int t = blockIdx.x * blockDim.x + threadIdx.x;
    if (blockIdx.x == 0 && threadIdx.x < NB_SCAN) g_state[threadIdx.x] = 0ULL;
    if (t < NNZ / 4) {
        const int4 r = __ldcs(&rows4[t]);
        atomicAdd(&g_cnt[r.x], 1);
        atomicAdd(&g_cnt[r.y], 1);
        atomicAdd(&g_cnt[r.z], 1);
        atomicAdd(&g_cnt[r.w], 1);
    }
}

// ---------------- single-pass exclusive scan with decoupled lookback ---------
__global__ void k_scan() {
    __shared__ int wsum[32];
    __shared__ int s_running;
    const int bid  = blockIdx.x;
    const int i    = bid * SCAN_BS + threadIdx.x;
    const int lane = threadIdx.x & 31;
    const int wid  = threadIdx.x >> 5;

    int v = (i < N_NODES) ? g_cnt[i] : 0;
    if (i < N_NODES) g_cnt[i] = 0;

    int s = v;
    #pragma unroll
    for (int d = 1; d < 32; d <<= 1) {
        int t = __shfl_up_sync(0xffffffffu, s, d);
        if (lane >= d) s += t;
    }
    if (lane == 31) wsum[wid] = s;
    __syncthreads();
    if (wid == 0) {
        int ws = wsum[lane];
        #pragma unroll
        for (int d = 1; d < 32; d <<= 1) {
            int t = __shfl_up_sync(0xffffffffu, ws, d);
            if (lane >= d) ws += t;
        }
        wsum[lane] = ws;
    }
    __syncthreads();
    const int incl  = s + (wid ? wsum[wid - 1] : 0);
    const int total = wsum[31];

    if (threadIdx.x == 0) {
        unsigned long long pk = ((bid == 0) ? (2ULL << 32) : (1ULL << 32))
                                | (unsigned)total;
        __threadfence();
        atomicExch(&g_state[bid], pk);
        if (bid == 0) { s_running = 0; g_rowptr[N_NODES] = NNZ; }
    }

    if (wid == 0 && bid > 0) {
        int running = 0;
        int pb = bid - 1;
        while (true) {
            int idx = pb - lane;
            unsigned long long st = 0ULL;
            if (idx >= 0) {
                do {
                    st = *(volatile unsigned long long*)&g_state[idx];
                } while ((st >> 32) == 0ULL);
            }
            unsigned pm = __ballot_sync(0xffffffffu, (idx >= 0) && ((st >> 32) == 2ULL));
            int val = (idx >= 0) ? (int)(st & 0xffffffffULL) : 0;
            if (pm) {
                int fp = __ffs(pm) - 1;
                int contrib = (lane <= fp) ? val : 0;
                #pragma unroll
                for (int m = 16; m; m >>= 1) contrib += __shfl_xor_sync(0xffffffffu, contrib, m);
                running += contrib;
                break;
            } else {
                int contrib = val;
                #pragma unroll
                for (int m = 16; m; m >>= 1) contrib += __shfl_xor_sync(0xffffffffu, contrib, m);
                running += contrib;
                pb -= 32;
            }
        }
        if (lane == 0) {
            __threadfence();
            atomicExch(&g_state[bid], (2ULL << 32) | (unsigned)(total + running));
            s_running = running;
        }
    }
    __syncthreads();

    const int excl = incl - v + s_running;
    if (i < N_NODES) { g_rowptr[i] = excl; g_cursor[i] = excl; }
}

// ---------------- scatter COO -> CSR: 4 edges/thread via vector loads --------
__global__ void k_scatter(const int4* __restrict__ rows4,
                          const int4* __restrict__ cols4,
                          const float4* __restrict__ vals4) {
    int t = blockIdx.x * blockDim.x + threadIdx.x;
    if (t < NNZ / 4) {
        const int4   r = __ldcs(&rows4[t]);
        const int4   c = __ldcs(&cols4[t]);
        const float4 v = __ldcs(&vals4[t]);
        int p;
        p = atomicAdd(&g_cursor[r.x], 1); g_edges[p] = make_int2(c.x, __float_as_int(v.x));
        p = atomicAdd(&g_cursor[r.y], 1); g_edges[p] = make_int2(c.y, __float_as_int(v.y));
        p = atomicAdd(&g_cursor[r.z], 1); g_edges[p] = make_int2(c.z, __float_as_int(v.z));
        p = atomicAdd(&g_cursor[r.w], 1); g_edges[p] = make_int2(c.w, __float_as_int(v.w));
    }
}

// ---------------- fused SpMM + noise-perturb + epilogue (EXACT R9) -----------
// TWO rows per warp via half-warps; lane holds a float4. Unguarded unroll-4
// with software-prefetched edge quads; 32-bit gather offsets. Noise loaded
// AFTER the edge walk (regs not live across the loop).
template <int K>
__global__ void __launch_bounds__(256, 7)
k_spmm(const float4* __restrict__ xu,
       const float4* __restrict__ xi_adj,          // xi - N_USERS*D4 (only formed)
       const float4* __restrict__ noise,           // offset to layer K
       const float4* __restrict__ prevA,           // K==2: ego1
       const float4* __restrict__ prevB,           // K==2: ego2
       float4* __restrict__ yout,                  // K==0/1
       float4* __restrict__ out4)                  // d_out as float4
{
    const int gw   = (blockIdx.x * blockDim.x + threadIdx.x) >> 5;
    const int lane = threadIdx.x & 31;
    const int half = lane >> 4;
    const unsigned fl = lane & 15;
    const int row  = gw * 2 + half;
    if (row >= N_NODES) return;

    int p   = __ldg(&g_rowptr[row]);
    int end = __ldg(&g_rowptr[row + 1]);

    float4 acc = make_float4(0.f, 0.f, 0.f, 0.f);

    #define GATHER(e) __ldg((((e).x < N_USERS) ? xu : xi_adj) + ((unsigned)(e).x * D4 + fl))
    #define FMA4(v, t) do { \
        acc.x = fmaf((v), (t).x, acc.x); \
        acc.y = fmaf((v), (t).y, acc.y); \
        acc.z = fmaf((v), (t).z, acc.z); \
        acc.w = fmaf((v), (t).w, acc.w); } while (0)

    if (p + 4 <= end) {
        int2 e0 = __ldg(&g_edges[p + 0]);
        int2 e1 = __ldg(&g_edges[p + 1]);
        int2 e2 = __ldg(&g_edges[p + 2]);
        int2 e3 = __ldg(&g_edges[p + 3]);
        for (; p + 8 <= end; p += 4) {
            const float4 t0 = GATHER(e0);
            const float4 t1 = GATHER(e1);
            const float4 t2 = GATHER(e2);
            const float4 t3 = GATHER(e3);
            const int2 n0 = __ldg(&g_edges[p + 4]);
            const int2 n1 = __ldg(&g_edges[p + 5]);
            const int2 n2 = __ldg(&g_edges[p + 6]);
            const int2 n3 = __ldg(&g_edges[p + 7]);
            FMA4(__int_as_float(e0.y), t0);
            FMA4(__int_as_float(e1.y), t1);
            FMA4(__int_as_float(e2.y), t2);
            FMA4(__int_as_float(e3.y), t3);
            e0 = n0; e1 = n1; e2 = n2; e3 = n3;
        }
        const float4 t0 = GATHER(e0);
        const float4 t1 = GATHER(e1);
        const float4 t2 = GATHER(e2);
        const float4 t3 = GATHER(e3);
        FMA4(__int_as_float(e0.y), t0);
        FMA4(__int_as_float(e1.y), t1);
        FMA4(__int_as_float(e2.y), t2);
        FMA4(__int_as_float(e3.y), t3);
        p += 4;
    }
    for (; p < end; ++p) {
        const int2 e0 = __ldg(&g_edges[p]);
        const float4 t0 = GATHER(e0);
        FMA4(__int_as_float(e0.y), t0);
    }
    #undef GATHER
    #undef FMA4

    const size_t off = (size_t)row * D4 + fl;
    const float4 nk  = __ldcs(noise + off);

    float ss = nk.x * nk.x + nk.y * nk.y + nk.z * nk.z + nk.w * nk.w;
    #pragma unroll
    for (int m = 8; m; m >>= 1) ss += __shfl_xor_sync(0xffffffffu, ss, m);
    const float inv = EPS / fmaxf(sqrtf(ss), 1e-12f);
    float4 r = acc;
    r.x += ((acc.x > 0.f) ? 1.f : ((acc.x < 0.f) ? -1.f : 0.f)) * nk.x * inv;
    r.y += ((acc.y > 0.f) ? 1.f : ((acc.y < 0.f) ? -1.f : 0.f)) * nk.y * inv;
    r.z += ((acc.z > 0.f) ? 1.f : ((acc.z < 0.f) ? -1.f : 0.f)) * nk.z * inv;
    r.w += ((acc.w > 0.f) ? 1.f : ((acc.w < 0.f) ? -1.f : 0.f)) * nk.w * inv;

    if (K == 0) {
        yout[off] = r;                                     // ego1 (reused next layer)
        __stcs(out4 + (size_t)N_NODES * D4 + off, r);      // CL region: stream out
    } else if (K == 1) {
        yout[off] = r;                                     // ego2
    } else {
        const float4 pa = __ldcs(prevA + off);             // ego1: last use
        const float4 pb = __ldg(prevB + off);              // ego2: L2-hot
        const float third = 1.f / 3.f;
        float4 f;
        f.x = (pa.x + pb.x + r.x) * third;
        f.y = (pa.y + pb.y + r.y) * third;
        f.z = (pa.z + pb.z + r.z) * third;
        f.w = (pa.w + pb.w + r.w) * third;
        __stcs(out4 + off, f);                             // final region: stream out
    }
}

// ---------------- launch ------------------------------------------------------
extern "C" void kernel_launch(void* const* d_in, const int* in_sizes, int n_in,
                              void* d_out, int out_size) {
    const float* user_emb = (const float*)d_in[0];
    const float* item_emb = (const float*)d_in[1];
    const float* adj_vals = (const float*)d_in[2];
    const float* noise    = (const float*)d_in[3];
    const int*   adj_rows = (const int*)d_in[4];
    const int*   adj_cols = (const int*)d_in[5];
    float4* out4 = (float4*)d_out;

    // --- build CSR from COO (vectorized: 4 edges per thread) ---
    const int eth = NNZ / 4;                               // 320000
    k_hist<<<(eth + 255) / 256, 256>>>((const int4*)adj_rows);
    k_scan<<<NB_SCAN, SCAN_BS>>>();
    k_scatter<<<(eth + 255) / 256, 256>>>((const int4*)adj_rows,
                                          (const int4*)adj_cols,
                                          (const float4*)adj_vals);

    static float4* ego1 = nullptr;
    static float4* ego2 = nullptr;
    if (!ego1) {
        void* p;
        cudaGetSymbolAddress(&p, g_ego1); ego1 = (float4*)p;
        cudaGetSymbolAddress(&p, g_ego2); ego2 = (float4*)p;
    }

    const float4* noise4 = (const float4*)noise;
    const int threads = 256;                               // 8 warps = 16 rows/block
    const int blocks  = N_NODES / 16;                      // 10000

    // layer 0: split tables; xi_adj = item_emb - N_USERS*D4 (pointer only formed)
    k_spmm<0><<<blocks, threads>>>((const float4*)user_emb,
                                   (const float4*)item_emb - (size_t)N_USERS * D4,
                                   noise4,
                                   nullptr, nullptr, ego1, out4);
    // layer 1: x = ego1 contiguous -> xi_adj == xu
    k_spmm<1><<<blocks, threads>>>((const float4*)ego1,
                                   (const float4*)ego1,
                                   noise4 + (size_t)1 * N_NODES * D4,
                                   nullptr, nullptr, ego2, out4);
    // layer 2: x = ego2; epilogue writes final = (ego1+ego2+ego3)/3
    k_spmm<2><<<blocks, threads>>>((const float4*)ego2,
                                   (const float4*)ego2,
                                   noise4 + (size_t)2 * N_NODES * D4,
                                   (const float4*)ego1, (const float4*)ego2,
                                   nullptr, out4);
}